// round 3
// baseline (speedup 1.0000x reference)
#include <cuda_runtime.h>
#include <math.h>

// Problem constants
// D_IN=42, H=800, L=256, B=16, ALPHA=20
#define LSEQ 256
#define HN   800
#define NB   16
#define G4   3200
#define NCTA 148
#define CPD  74          // CTAs per direction

// ---------------- scratch (device globals; no allocations allowed) ----------
static __device__ float g_g0[2*LSEQ*G4*NB];     // layer0 input proj, [dir][t][j][b]
static __device__ float g_g1[2*LSEQ*G4*NB];     // layer1 input proj, [dir][t][j][b]
static __device__ float g_h1[LSEQ*NB*1600];     // layer0 output  [t][b][2H]
static __device__ float g_h2[LSEQ*NB*1600];     // layer1 output  [t][b][2H]
static __device__ float g_hping[2*2*NB*HN];     // [parity][dir][b][u]
static __device__ float g_ang[LSEQ*NB*3];       // torsion angles
static __device__ unsigned g_bar[1024];         // barrier slots (zeroed each run)

__device__ __forceinline__ float sigf(float x){ return 1.0f/(1.0f+expf(-x)); }

// ---------------- grid-wide barrier (one fresh slot per use) ----------------
__device__ __forceinline__ void gbar(int idx){
    __syncthreads();
    if (threadIdx.x == 0){
        __threadfence();
        atomicAdd(&g_bar[idx], 1u);
        volatile unsigned* vb = &g_bar[idx];
        while (*vb < (unsigned)NCTA) { }
        __threadfence();
    }
    __syncthreads();
}

// ---------------- kernel 1: layer-0 input projection (K=42) -----------------
// g0[dir][t][j][b] = x[b,t,:] . wih0[dir,j,:] + b0[dir,j]
__global__ void proj0_kernel(const float* __restrict__ x,
                             const float* __restrict__ wih,
                             const float* __restrict__ bias){
    const int t = blockIdx.x, dir = blockIdx.y;
    const int tid = threadIdx.x;
    __shared__ float sx[16*42];
    if (t == 0 && dir == 0){
        for (int i = tid; i < 1024; i += 256) g_bar[i] = 0u;  // reset barriers each run
    }
    for (int i = tid; i < 16*42; i += 256){
        int bb = i / 42, d = i - bb*42;
        sx[i] = x[(bb*LSEQ + t)*42 + d];
    }
    __syncthreads();
    for (int j = tid; j < G4; j += 256){
        const float* w = &wih[(dir*G4 + j)*42];
        float wr[42];
#pragma unroll
        for (int d = 0; d < 42; d++) wr[d] = w[d];
        float bv = bias[dir*G4 + j];
        float* gout = &g_g0[(((size_t)dir*LSEQ + t)*G4 + j)*NB];
        for (int bb = 0; bb < 16; bb++){
            float acc = bv;
#pragma unroll
            for (int d = 0; d < 42; d++) acc = fmaf(wr[d], sx[bb*42 + d], acc);
            gout[bb] = acc;
        }
    }
}

// ---------------- kernel 2: persistent bi-LSTM layer ------------------------
// grid = 148 CTAs, all resident. CTAs [0,74) = fwd, [74,148) = bwd.
// Each CTA owns ~10-11 hidden units (all 4 gate rows), keeps cell state in smem.
// Hidden state double-buffered in global, read via __ldcg (L1 not coherent).
__global__ void __launch_bounds__(256,1) lstm_kernel(
    const float* __restrict__ whh,   // [2][3200][800]
    int layer, int bar_base)
{
    __shared__ float sh[16*404];     // half of h (16 x 400) + pad
    __shared__ float sgate[44*16];
    __shared__ float sc[176];        // cell state slice [uu][b]

    const float* gin  = (layer == 0) ? g_g0 : g_g1;
    float*       hseq = (layer == 0) ? g_h1 : g_h2;

    const int cta = blockIdx.x;
    const int dir = cta / CPD;
    const int lc  = cta - dir*CPD;
    const int u0  = (lc*HN)/CPD;
    const int n_u = ((lc+1)*HN)/CPD - u0;
    const int n_rows = 4*n_u;
    const int tid = threadIdx.x;
    const int b   = tid & 15;
    const int rs  = tid >> 4;

    // per-run init: zero my slice of h (parity 0) and cell state
    if (tid < n_u*16){
        int uu = tid >> 4, bb = tid & 15;
        sc[tid] = 0.f;
        g_hping[(dir*NB + bb)*HN + u0 + uu] = 0.f;
    }
    gbar(bar_base);

    int p = 0;
    for (int s = 0; s < LSEQ; s++){
        const int t = dir ? (LSEQ-1-s) : s;
        float part[3];
        {   // seed with input projection (bias folded in)
            const float* gi = gin + ((size_t)(dir*LSEQ + t)*G4)*NB;
            int cnt = 0;
            for (int r = rs; r < n_rows; r += 16){
                int q = r & 3, uu = r >> 2;
                int j = q*HN + u0 + uu;
                part[cnt++] = gi[(size_t)j*NB + b];
            }
        }
        // K split in two halves of 400 to keep smem < 48KB
        for (int kh = 0; kh < 2; kh++){
            for (int idx = tid; idx < 1600; idx += 256){
                int bb = idx / 100;
                int k4 = idx - bb*100;
                float4 v = __ldcg((const float4*)&g_hping[((p*2 + dir)*NB + bb)*HN + kh*400 + k4*4]);
                *(float4*)&sh[bb*404 + k4*4] = v;
            }
            __syncthreads();
            int cnt = 0;
            for (int r = rs; r < n_rows; r += 16){
                int q = r & 3, uu = r >> 2;
                int j = q*HN + u0 + uu;
                const float4* wr = (const float4*)&whh[((size_t)(dir*G4 + j))*HN + kh*400];
                const float4* hr = (const float4*)&sh[b*404];
                float a0=0.f,a1=0.f,a2=0.f,a3=0.f;
#pragma unroll 4
                for (int k4 = 0; k4 < 100; k4++){
                    float4 w = wr[k4];
                    float4 h = hr[k4];
                    a0 = fmaf(w.x, h.x, a0); a1 = fmaf(w.y, h.y, a1);
                    a2 = fmaf(w.z, h.z, a2); a3 = fmaf(w.w, h.w, a3);
                }
                part[cnt++] += (a0 + a1) + (a2 + a3);
            }
            __syncthreads();
        }
        {
            int cnt = 0;
            for (int r = rs; r < n_rows; r += 16) sgate[r*16 + b] = part[cnt++];
        }
        __syncthreads();
        if (tid < n_u*16){
            int uu = tid >> 4, bb = tid & 15;
            float giv = sgate[(uu*4 + 0)*16 + bb];
            float gf  = sgate[(uu*4 + 1)*16 + bb];
            float gg  = sgate[(uu*4 + 2)*16 + bb];
            float go  = sgate[(uu*4 + 3)*16 + bb];
            float c = sigf(gf)*sc[tid] + sigf(giv)*tanhf(gg);
            sc[tid] = c;
            float hv = sigf(go)*tanhf(c);
            int u = u0 + uu;
            g_hping[(((p^1)*2 + dir)*NB + bb)*HN + u] = hv;
            hseq[(t*NB + bb)*1600 + dir*HN + u] = hv;
        }
        p ^= 1;
        gbar(bar_base + 1 + s);
    }
}

// ---------------- kernel 3: layer-1 input projection (big SGEMM) ------------
// C[m][n] = sum_k h1[m][k] * wih1[dir][j][k] ; M=4096, Nper dir=3200, K=1600
__global__ void __launch_bounds__(256) gemm1_kernel(
    const float* __restrict__ wih,   // [2][3200][1600]
    const float* __restrict__ bias)  // [2][3200]
{
    __shared__ float As[16][132];
    __shared__ float Bs[16][132];
    const int tid = threadIdx.x;
    const int mtile = blockIdx.x;             // 0..31
    const int nt    = blockIdx.y;             // 0..49
    const int dir   = nt / 25;
    const int jbase = (nt - dir*25)*128;
    const int m0    = mtile*128;
    const int lrow  = tid >> 1;
    const int lf4   = (tid & 1)*2;
    const int tx    = tid & 15;
    const int ty    = tid >> 4;
    const float* Ab = g_h1 + (size_t)m0*1600;
    const float* Bb = wih + ((size_t)(dir*G4 + jbase))*1600;
    float acc[8][8];
#pragma unroll
    for (int i = 0; i < 8; i++)
#pragma unroll
        for (int j = 0; j < 8; j++) acc[i][j] = 0.f;

    for (int k0 = 0; k0 < 1600; k0 += 16){
#pragma unroll
        for (int hh = 0; hh < 2; hh++){
            float4 va = *(const float4*)&Ab[(size_t)lrow*1600 + k0 + (lf4+hh)*4];
            float4 vb = *(const float4*)&Bb[(size_t)lrow*1600 + k0 + (lf4+hh)*4];
            int kk = (lf4+hh)*4;
            As[kk+0][lrow]=va.x; As[kk+1][lrow]=va.y; As[kk+2][lrow]=va.z; As[kk+3][lrow]=va.w;
            Bs[kk+0][lrow]=vb.x; Bs[kk+1][lrow]=vb.y; Bs[kk+2][lrow]=vb.z; Bs[kk+3][lrow]=vb.w;
        }
        __syncthreads();
#pragma unroll
        for (int kk = 0; kk < 16; kk++){
            float4 a0 = *(const float4*)&As[kk][ty*4];
            float4 a1 = *(const float4*)&As[kk][64 + ty*4];
            float4 b0 = *(const float4*)&Bs[kk][tx*4];
            float4 b1 = *(const float4*)&Bs[kk][64 + tx*4];
            float am[8] = {a0.x,a0.y,a0.z,a0.w,a1.x,a1.y,a1.z,a1.w};
            float bn[8] = {b0.x,b0.y,b0.z,b0.w,b1.x,b1.y,b1.z,b1.w};
#pragma unroll
            for (int i = 0; i < 8; i++)
#pragma unroll
                for (int j = 0; j < 8; j++) acc[i][j] = fmaf(am[i], bn[j], acc[i][j]);
        }
        __syncthreads();
    }
#pragma unroll
    for (int i = 0; i < 8; i++){
        int mi = (i < 4) ? (ty*4 + i) : (64 + ty*4 + i - 4);
        int m  = m0 + mi;
        int t  = m >> 4, bb = m & 15;
#pragma unroll
        for (int j = 0; j < 8; j++){
            int nj = (j < 4) ? (tx*4 + j) : (64 + tx*4 + j - 4);
            int jj = jbase + nj;
            g_g1[(((size_t)dir*LSEQ + t)*G4 + jj)*NB + bb] = acc[i][j] + bias[dir*G4 + jj];
        }
    }
}

// ---------------- kernel 4: head (logits -> softmax -> angles) --------------
__global__ void head_kernel(const float* __restrict__ wlin,
                            const float* __restrict__ blin,
                            const float* __restrict__ alphabet){
    const int t = blockIdx.x;
    const int tid = threadIdx.x;   // 320 threads
    __shared__ float slog[16][20];
    __shared__ float smax[16];
    __shared__ float sexp[16][20];
    __shared__ float ssin[20][3], scos[20][3];
    if (tid < 60){
        int a = tid / 3, i = tid - a*3;
        float v = alphabet[a*3 + i];
        ssin[a][i] = sinf(v); scos[a][i] = cosf(v);
    }
    const int a = tid % 20, b = tid / 20;   // b in [0,16)
    float acc = blin[a];
    const float4* hr = (const float4*)&g_h2[((size_t)(t*NB + b))*1600];
    const float4* wr = (const float4*)&wlin[(size_t)a*1600];
    for (int k = 0; k < 400; k++){
        float4 h = hr[k], w = wr[k];
        acc = fmaf(h.x, w.x, acc); acc = fmaf(h.y, w.y, acc);
        acc = fmaf(h.z, w.z, acc); acc = fmaf(h.w, w.w, acc);
    }
    slog[b][a] = acc;
    __syncthreads();
    if (tid < 16){
        float m = -1e30f;
        for (int q = 0; q < 20; q++) m = fmaxf(m, slog[tid][q]);
        smax[tid] = m;
    }
    __syncthreads();
    sexp[b][a] = expf(slog[b][a] - smax[b]);
    __syncthreads();
    if (tid < 48){
        int bb = tid / 3, i = tid - bb*3;
        float s = 0.f, c = 0.f;
        for (int q = 0; q < 20; q++){
            float pv = sexp[bb][q];
            s = fmaf(pv, ssin[q][i], s);
            c = fmaf(pv, scos[q][i], c);
        }
        // softmax normalizer cancels inside atan2 (positive scale)
        g_ang[(t*NB + bb)*3 + i] = atan2f(s, c);
    }
}

// ---------------- kernel 5: sequential coordinate chain (NeRF) --------------
__global__ void coords_kernel(float* __restrict__ out){
    const int b = threadIdx.x;
    if (b >= 16) return;
    const float Rv[3] = {145.801f, 152.326f, 132.868f};
    const float Tv[3] = {2.124f, 1.941f, 2.028f};
    float cT[3], sT[3];
#pragma unroll
    for (int i = 0; i < 3; i++){ cT[i] = cosf(Tv[i]); sT[i] = sinf(Tv[i]); }
    float Ax=0.f,Ay=0.f,Az=1.f, Bx=0.f,By=1.f,Bz=0.f, Cx=1.f,Cy=0.f,Cz=0.f;
    // init rows: A0, B0, C0
    out[(0*16+b)*3+0]=0.f; out[(0*16+b)*3+1]=0.f; out[(0*16+b)*3+2]=1.f;
    out[(1*16+b)*3+0]=0.f; out[(1*16+b)*3+1]=1.f; out[(1*16+b)*3+2]=0.f;
    out[(2*16+b)*3+0]=1.f; out[(2*16+b)*3+1]=0.f; out[(2*16+b)*3+2]=0.f;
    for (int tt = 0; tt < LSEQ; tt++){
#pragma unroll
        for (int i = 0; i < 3; i++){
            float P = g_ang[(tt*NB + b)*3 + i];
            float sp, cp; sincosf(P, &sp, &cp);
            float d2x = -Rv[i]*cT[i];
            float d2y =  Rv[i]*cp*sT[i];
            float d2z =  Rv[i]*sp*sT[i];
            float bcx = Cx-Bx, bcy = Cy-By, bcz = Cz-Bz;
            float inv = rsqrtf(bcx*bcx + bcy*bcy + bcz*bcz);
            bcx *= inv; bcy *= inv; bcz *= inv;
            float abx = Bx-Ax, aby = By-Ay, abz = Bz-Az;
            float nx = aby*bcz - abz*bcy;
            float ny = abz*bcx - abx*bcz;
            float nz = abx*bcy - aby*bcx;
            float invn = rsqrtf(nx*nx + ny*ny + nz*nz);
            nx *= invn; ny *= invn; nz *= invn;
            float mx = ny*bcz - nz*bcy;
            float my = nz*bcx - nx*bcz;
            float mz = nx*bcy - ny*bcx;
            float Dx = bcx*d2x + mx*d2y + nx*d2z + Cx;
            float Dy = bcy*d2x + my*d2y + ny*d2z + Cy;
            float Dz = bcz*d2x + mz*d2y + nz*d2z + Cz;
            int row = 3 + tt*3 + i;
            out[(row*16 + b)*3 + 0] = Dx;
            out[(row*16 + b)*3 + 1] = Dy;
            out[(row*16 + b)*3 + 2] = Dz;
            Ax=Bx; Ay=By; Az=Bz;
            Bx=Cx; By=Cy; Bz=Cz;
            Cx=Dx; Cy=Dy; Cz=Dz;
        }
    }
}

// ---------------- launch --------------------------------------------------
extern "C" void kernel_launch(void* const* d_in, const int* in_sizes, int n_in,
                              void* d_out, int out_size){
    const float* x    = (const float*)d_in[0];
    const float* wih0 = (const float*)d_in[1];
    const float* whh0 = (const float*)d_in[2];
    const float* b0   = (const float*)d_in[3];
    const float* wih1 = (const float*)d_in[4];
    const float* whh1 = (const float*)d_in[5];
    const float* b1   = (const float*)d_in[6];
    const float* wlin = (const float*)d_in[7];
    const float* blin = (const float*)d_in[8];
    const float* alph = (const float*)d_in[9];
    float* out = (float*)d_out;

    proj0_kernel<<<dim3(LSEQ,2),256>>>(x, wih0, b0);         // also resets barriers
    lstm_kernel<<<NCTA,256>>>(whh0, 0, 0);                   // layer 0 (persistent)
    gemm1_kernel<<<dim3(32,50),256>>>(wih1, b1);             // layer-1 input proj
    lstm_kernel<<<NCTA,256>>>(whh1, 1, 512);                 // layer 1 (persistent)
    head_kernel<<<LSEQ,320>>>(wlin, blin, alph);             // angles
    coords_kernel<<<1,32>>>(out);                            // coordinate chain
}

// round 4
// speedup vs baseline: 2.0253x; 2.0253x over previous
#include <cuda_runtime.h>
#include <math.h>

// D_IN=42, H=800, L=256, B=16, ALPHA=20
#define LSEQ 256
#define HN   800
#define NB   16
#define G4   3200
#define NCTA 148
#define CPD  74
#define SWS  804                       // padded smem row stride (floats)
#define MAXR 44
#define SH_OFF (MAXR*SWS)              // h buffer offset in dynamic smem (floats)
#define LSTM_SMEM_BYTES ((MAXR*SWS + 16*SWS)*4)   // 192960 B

// ---------------- scratch (device globals; no allocations allowed) ----------
static __device__ float g_g0[2*LSEQ*G4*NB];
static __device__ float g_g1[2*LSEQ*G4*NB];
static __device__ float g_h1[LSEQ*NB*1600];
static __device__ float g_h2[LSEQ*NB*1600];
static __device__ float g_hping[2*2*NB*HN];
static __device__ float g_ang[LSEQ*NB*3];
static __device__ unsigned g_bar[1024];

__device__ __forceinline__ float sigf(float x){ return 1.0f/(1.0f+expf(-x)); }

// packed fp32x2 FMA (bit-exact fp32, 2 lanes per instruction)
__device__ __forceinline__ unsigned long long ffma2(unsigned long long a,
                                                    unsigned long long b,
                                                    unsigned long long c){
    unsigned long long d;
    asm("fma.rn.f32x2 %0, %1, %2, %3;" : "=l"(d) : "l"(a), "l"(b), "l"(c));
    return d;
}

// ---------------- grid-wide barrier ----------------------------------------
__device__ __forceinline__ void gbar(int idx){
    __syncthreads();
    if (threadIdx.x == 0){
        __threadfence();
        atomicAdd(&g_bar[idx], 1u);
        volatile unsigned* vb = &g_bar[idx];
        while (*vb < (unsigned)NCTA) { }
        __threadfence();
    }
    __syncthreads();
}

// ---------------- kernel 1: layer-0 input projection (K=42) -----------------
__global__ void proj0_kernel(const float* __restrict__ x,
                             const float* __restrict__ wih,
                             const float* __restrict__ bias){
    const int t = blockIdx.x, dir = blockIdx.y;
    const int tid = threadIdx.x;
    __shared__ float sx[16*42];
    if (t == 0 && dir == 0){
        for (int i = tid; i < 1024; i += 256) g_bar[i] = 0u;
    }
    for (int i = tid; i < 16*42; i += 256){
        int bb = i / 42, d = i - bb*42;
        sx[i] = x[(bb*LSEQ + t)*42 + d];
    }
    __syncthreads();
    for (int j = tid; j < G4; j += 256){
        const float* w = &wih[(dir*G4 + j)*42];
        float wr[42];
#pragma unroll
        for (int d = 0; d < 42; d++) wr[d] = w[d];
        float bv = bias[dir*G4 + j];
        float* gout = &g_g0[(((size_t)dir*LSEQ + t)*G4 + j)*NB];
        for (int bb = 0; bb < 16; bb++){
            float acc = bv;
#pragma unroll
            for (int d = 0; d < 42; d++) acc = fmaf(wr[d], sx[bb*42 + d], acc);
            gout[bb] = acc;
        }
    }
}

// ---------------- kernel 2: persistent bi-LSTM, weight-stationary in SMEM ---
__global__ void __launch_bounds__(256,1) lstm_kernel(
    const float* __restrict__ whh,   // [2][3200][800]
    int layer, int bar_base)
{
    extern __shared__ float dsm[];           // [sw: 44x804][sh: 16x804]
    __shared__ float sgate[MAXR*16];
    __shared__ float sc[176];

    const float* gin  = layer ? g_g1 : g_g0;
    float*       hseq = layer ? g_h2 : g_h1;

    const int cta = blockIdx.x;
    const int dir = cta / CPD;
    const int lc  = cta - dir*CPD;
    const int u0  = (lc*HN)/CPD;
    const int n_u = ((lc+1)*HN)/CPD - u0;
    const int n_rows = 4*n_u;                // 40 or 44
    const int tid = threadIdx.x;
    const int b   = tid & 15;
    const int slot= tid >> 4;

    float* sw = dsm;
    float* sh = dsm + SH_OFF;

    // one-time weight preload into SMEM (local row r = 4*uu + q  <->  j = q*HN+u0+uu)
    for (int i = tid; i < n_rows*200; i += 256){
        int r = i / 200, k4 = i - r*200;
        int q = r & 3, uu = r >> 2;
        int j = q*HN + u0 + uu;
        *(float4*)&sw[r*SWS + k4*4] =
            *(const float4*)&whh[((size_t)(dir*G4 + j))*HN + k4*4];
    }
    if (tid < n_u*16){
        sc[tid] = 0.f;
        g_hping[(dir*NB + (tid & 15))*HN + u0 + (tid >> 4)] = 0.f;
    }
    gbar(bar_base);   // also covers smem preload visibility within CTA

    // my rows: r = slot, slot+16, slot+32 (2 or 3 of them)
    int nr = 0; int rofs[3]; int jrow[3];
    for (int r = slot; r < n_rows; r += 16){
        rofs[nr] = r*SWS;
        jrow[nr] = (r & 3)*HN + u0 + (r >> 2);
        nr++;
    }
    const ulonglong2* wp0 = (const ulonglong2*)&sw[rofs[0]];
    const ulonglong2* wp1 = (const ulonglong2*)&sw[rofs[1]];
    const ulonglong2* wp2 = (const ulonglong2*)&sw[rofs[(nr > 2) ? 2 : 0]];

    int p = 0;
    for (int s = 0; s < LSEQ; s++){
        const int t = dir ? (LSEQ-1-s) : s;
        // broadcast full h (16x800) into smem from global ping buffer
        for (int idx = tid; idx < 3200; idx += 256){
            int bb = idx / 200, k4 = idx - bb*200;
            float4 v = __ldcg((const float4*)&g_hping[((p*2 + dir)*NB + bb)*HN + k4*4]);
            *(float4*)&sh[bb*SWS + k4*4] = v;
        }
        __syncthreads();

        unsigned long long a00=0ull,a01=0ull,a10=0ull,a11=0ull,a20=0ull,a21=0ull;
        const ulonglong2* hp = (const ulonglong2*)&sh[b*SWS];
#pragma unroll 2
        for (int k4 = 0; k4 < 200; k4++){
            ulonglong2 h2 = hp[k4];
            ulonglong2 w0 = wp0[k4];
            a00 = ffma2(w0.x, h2.x, a00); a01 = ffma2(w0.y, h2.y, a01);
            ulonglong2 w1 = wp1[k4];
            a10 = ffma2(w1.x, h2.x, a10); a11 = ffma2(w1.y, h2.y, a11);
            ulonglong2 w2 = wp2[k4];
            a20 = ffma2(w2.x, h2.x, a20); a21 = ffma2(w2.y, h2.y, a21);
        }
        {
            const float* gi = gin + ((size_t)(dir*LSEQ + t)*G4)*NB;
            float2 x0, x1;
            x0 = *(float2*)&a00; x1 = *(float2*)&a01;
            sgate[(slot)*16 + b]      = (x0.x + x0.y) + (x1.x + x1.y)
                                        + gi[(size_t)jrow[0]*NB + b];
            x0 = *(float2*)&a10; x1 = *(float2*)&a11;
            sgate[(slot+16)*16 + b]   = (x0.x + x0.y) + (x1.x + x1.y)
                                        + gi[(size_t)jrow[1]*NB + b];
            if (nr > 2){
                x0 = *(float2*)&a20; x1 = *(float2*)&a21;
                sgate[(slot+32)*16 + b] = (x0.x + x0.y) + (x1.x + x1.y)
                                          + gi[(size_t)jrow[2]*NB + b];
            }
        }
        __syncthreads();
        if (tid < n_u*16){
            int uu = tid >> 4, bb = tid & 15;
            float giv = sgate[(uu*4 + 0)*16 + bb];
            float gf  = sgate[(uu*4 + 1)*16 + bb];
            float gg  = sgate[(uu*4 + 2)*16 + bb];
            float go  = sgate[(uu*4 + 3)*16 + bb];
            float c = sigf(gf)*sc[tid] + sigf(giv)*tanhf(gg);
            sc[tid] = c;
            float hv = sigf(go)*tanhf(c);
            int u = u0 + uu;
            g_hping[(((p^1)*2 + dir)*NB + bb)*HN + u] = hv;
            hseq[(t*NB + bb)*1600 + dir*HN + u] = hv;
        }
        p ^= 1;
        gbar(bar_base + 1 + s);
    }
}

// ---------------- kernel 3: layer-1 input projection (packed-f32x2 SGEMM) ---
// C[m][n] = sum_k h1[m][k] * wih1[dir][j][k] ; M=4096, N=3200/dir, K=1600
__global__ void __launch_bounds__(256) gemm1_kernel(
    const float* __restrict__ wih,   // [2][3200][1600]
    const float* __restrict__ bias)  // [2][3200]
{
    __shared__ float As[16*132];
    __shared__ float Bsd[16*260];     // B duplicated: Bsd[kk][2n]=Bsd[kk][2n+1]=B[kk][n]
    const int tid = threadIdx.x;
    const int mtile = blockIdx.x;             // 0..31
    const int nt    = blockIdx.y;             // 0..49
    const int dir   = nt / 25;
    const int jbase = (nt - dir*25)*128;
    const int m0    = mtile*128;
    const int lrow  = tid >> 1;
    const int lf4   = (tid & 1)*2;
    const int tx    = tid & 15;
    const int ty    = tid >> 4;
    const float* Ab = g_h1 + (size_t)m0*1600;
    const float* Bb = wih + ((size_t)(dir*G4 + jbase))*1600;

    unsigned long long acc[4][8];     // [m-pair][n]
#pragma unroll
    for (int i = 0; i < 4; i++)
#pragma unroll
        for (int j = 0; j < 8; j++) acc[i][j] = 0ull;

    for (int k0 = 0; k0 < 1600; k0 += 16){
#pragma unroll
        for (int hh = 0; hh < 2; hh++){
            float4 va = *(const float4*)&Ab[(size_t)lrow*1600 + k0 + (lf4+hh)*4];
            float4 vb = *(const float4*)&Bb[(size_t)lrow*1600 + k0 + (lf4+hh)*4];
            int kk = (lf4+hh)*4;
            As[(kk+0)*132 + lrow] = va.x;
            As[(kk+1)*132 + lrow] = va.y;
            As[(kk+2)*132 + lrow] = va.z;
            As[(kk+3)*132 + lrow] = va.w;
            *(float2*)&Bsd[(kk+0)*260 + 2*lrow] = make_float2(vb.x, vb.x);
            *(float2*)&Bsd[(kk+1)*260 + 2*lrow] = make_float2(vb.y, vb.y);
            *(float2*)&Bsd[(kk+2)*260 + 2*lrow] = make_float2(vb.z, vb.z);
            *(float2*)&Bsd[(kk+3)*260 + 2*lrow] = make_float2(vb.w, vb.w);
        }
        __syncthreads();
#pragma unroll
        for (int kk = 0; kk < 16; kk++){
            ulonglong2 a01 = *(const ulonglong2*)&As[kk*132 + ty*4];
            ulonglong2 a23 = *(const ulonglong2*)&As[kk*132 + 64 + ty*4];
            unsigned long long Ar[4] = {a01.x, a01.y, a23.x, a23.y};
            ulonglong2 b0 = *(const ulonglong2*)&Bsd[kk*260 + 8*tx];
            ulonglong2 b1 = *(const ulonglong2*)&Bsd[kk*260 + 8*tx + 4];
            ulonglong2 b2 = *(const ulonglong2*)&Bsd[kk*260 + 128 + 8*tx];
            ulonglong2 b3 = *(const ulonglong2*)&Bsd[kk*260 + 128 + 8*tx + 4];
            unsigned long long Br[8] = {b0.x,b0.y,b1.x,b1.y,b2.x,b2.y,b3.x,b3.y};
#pragma unroll
            for (int i = 0; i < 4; i++)
#pragma unroll
                for (int j = 0; j < 8; j++) acc[i][j] = ffma2(Ar[i], Br[j], acc[i][j]);
        }
        __syncthreads();
    }
#pragma unroll
    for (int i = 0; i < 4; i++){
        int mi0 = (i < 2) ? (ty*4 + 2*i) : (64 + ty*4 + 2*(i-2));
        int m   = m0 + mi0;
        int t   = m >> 4, bb = m & 15;        // bb even; pair (bb,bb+1) same t
#pragma unroll
        for (int j = 0; j < 8; j++){
            int nj = (j < 4) ? (tx*4 + j) : (64 + tx*4 + (j-4));
            int jj = jbase + nj;
            float2 v = *(float2*)&acc[i][j];
            float bv = bias[dir*G4 + jj];
            v.x += bv; v.y += bv;
            *(float2*)&g_g1[(((size_t)dir*LSEQ + t)*G4 + jj)*NB + bb] = v;
        }
    }
}

// ---------------- kernel 4: head (logits -> softmax -> angles) --------------
__global__ void head_kernel(const float* __restrict__ wlin,
                            const float* __restrict__ blin,
                            const float* __restrict__ alphabet){
    const int t = blockIdx.x;
    const int tid = threadIdx.x;   // 320 threads
    __shared__ float slog[16][20];
    __shared__ float smax[16];
    __shared__ float sexp[16][20];
    __shared__ float ssin[20][3], scos[20][3];
    if (tid < 60){
        int a = tid / 3, i = tid - a*3;
        float v = alphabet[a*3 + i];
        ssin[a][i] = sinf(v); scos[a][i] = cosf(v);
    }
    const int a = tid % 20, b = tid / 20;
    float acc = blin[a];
    const float4* hr = (const float4*)&g_h2[((size_t)(t*NB + b))*1600];
    const float4* wr = (const float4*)&wlin[(size_t)a*1600];
    for (int k = 0; k < 400; k++){
        float4 h = hr[k], w = wr[k];
        acc = fmaf(h.x, w.x, acc); acc = fmaf(h.y, w.y, acc);
        acc = fmaf(h.z, w.z, acc); acc = fmaf(h.w, w.w, acc);
    }
    slog[b][a] = acc;
    __syncthreads();
    if (tid < 16){
        float m = -1e30f;
        for (int q = 0; q < 20; q++) m = fmaxf(m, slog[tid][q]);
        smax[tid] = m;
    }
    __syncthreads();
    sexp[b][a] = expf(slog[b][a] - smax[b]);
    __syncthreads();
    if (tid < 48){
        int bb = tid / 3, i = tid - bb*3;
        float s = 0.f, c = 0.f;
        for (int q = 0; q < 20; q++){
            float pv = sexp[bb][q];
            s = fmaf(pv, ssin[q][i], s);
            c = fmaf(pv, scos[q][i], c);
        }
        g_ang[(t*NB + bb)*3 + i] = atan2f(s, c);
    }
}

// ---------------- kernel 5: sequential coordinate chain (NeRF) --------------
__global__ void coords_kernel(float* __restrict__ out){
    const int b = threadIdx.x;
    if (b >= 16) return;
    const float Rv[3] = {145.801f, 152.326f, 132.868f};
    const float Tv[3] = {2.124f, 1.941f, 2.028f};
    float cT[3], sT[3];
#pragma unroll
    for (int i = 0; i < 3; i++){ cT[i] = cosf(Tv[i]); sT[i] = sinf(Tv[i]); }
    float Ax=0.f,Ay=0.f,Az=1.f, Bx=0.f,By=1.f,Bz=0.f, Cx=1.f,Cy=0.f,Cz=0.f;
    out[(0*16+b)*3+0]=0.f; out[(0*16+b)*3+1]=0.f; out[(0*16+b)*3+2]=1.f;
    out[(1*16+b)*3+0]=0.f; out[(1*16+b)*3+1]=1.f; out[(1*16+b)*3+2]=0.f;
    out[(2*16+b)*3+0]=1.f; out[(2*16+b)*3+1]=0.f; out[(2*16+b)*3+2]=0.f;
    for (int tt = 0; tt < LSEQ; tt++){
#pragma unroll
        for (int i = 0; i < 3; i++){
            float P = g_ang[(tt*NB + b)*3 + i];
            float sp, cp; sincosf(P, &sp, &cp);
            float d2x = -Rv[i]*cT[i];
            float d2y =  Rv[i]*cp*sT[i];
            float d2z =  Rv[i]*sp*sT[i];
            float bcx = Cx-Bx, bcy = Cy-By, bcz = Cz-Bz;
            float inv = rsqrtf(bcx*bcx + bcy*bcy + bcz*bcz);
            bcx *= inv; bcy *= inv; bcz *= inv;
            float abx = Bx-Ax, aby = By-Ay, abz = Bz-Az;
            float nx = aby*bcz - abz*bcy;
            float ny = abz*bcx - abx*bcz;
            float nz = abx*bcy - aby*bcx;
            float invn = rsqrtf(nx*nx + ny*ny + nz*nz);
            nx *= invn; ny *= invn; nz *= invn;
            float mx = ny*bcz - nz*bcy;
            float my = nz*bcx - nx*bcz;
            float mz = nx*bcy - ny*bcx;
            float Dx = bcx*d2x + mx*d2y + nx*d2z + Cx;
            float Dy = bcy*d2x + my*d2y + ny*d2z + Cy;
            float Dz = bcz*d2x + mz*d2y + nz*d2z + Cz;
            int row = 3 + tt*3 + i;
            out[(row*16 + b)*3 + 0] = Dx;
            out[(row*16 + b)*3 + 1] = Dy;
            out[(row*16 + b)*3 + 2] = Dz;
            Ax=Bx; Ay=By; Az=Bz;
            Bx=Cx; By=Cy; Bz=Cz;
            Cx=Dx; Cy=Dy; Cz=Dz;
        }
    }
}

// ---------------- launch ----------------------------------------------------
extern "C" void kernel_launch(void* const* d_in, const int* in_sizes, int n_in,
                              void* d_out, int out_size){
    const float* x    = (const float*)d_in[0];
    const float* wih0 = (const float*)d_in[1];
    const float* whh0 = (const float*)d_in[2];
    const float* b0   = (const float*)d_in[3];
    const float* wih1 = (const float*)d_in[4];
    const float* whh1 = (const float*)d_in[5];
    const float* b1   = (const float*)d_in[6];
    const float* wlin = (const float*)d_in[7];
    const float* blin = (const float*)d_in[8];
    const float* alph = (const float*)d_in[9];
    float* out = (float*)d_out;

    cudaFuncSetAttribute(lstm_kernel,
                         cudaFuncAttributeMaxDynamicSharedMemorySize,
                         LSTM_SMEM_BYTES);

    proj0_kernel<<<dim3(LSEQ,2),256>>>(x, wih0, b0);              // + barrier reset
    lstm_kernel<<<NCTA,256,LSTM_SMEM_BYTES>>>(whh0, 0, 0);        // layer 0
    gemm1_kernel<<<dim3(32,50),256>>>(wih1, b1);                  // layer-1 input proj
    lstm_kernel<<<NCTA,256,LSTM_SMEM_BYTES>>>(whh1, 1, 512);      // layer 1
    head_kernel<<<LSEQ,320>>>(wlin, blin, alph);                  // angles
    coords_kernel<<<1,32>>>(out);                                 // coordinate chain
}